// round 9
// baseline (speedup 1.0000x reference)
#include <cuda_runtime.h>
#include <cstdint>

// Problem constants (match reference)
#define N_ATOMS 4096
#define NB 4095
#define NA 4094
#define NT 4093
#define MAX_LEN (5 * NT)          // 20465 rows
#define TOTAL_WORDS (MAX_LEN * 9) // 184185 words per sample (== 1 mod 4)
#define COORD_ROWS (3 * N_ATOMS)  // 12288
#define BOND_ROWS  (3 * NB)       // 12285
#define ANG_ROWS   (4 * NA)       // 16376
#define EPSF 1e-8f

#define NTHREADS 1024
#define CHUNK_ROWS 512
#define CHUNK_WORDS (CHUNK_ROWS * 9)              // 4608 words = 18432 B (== 0 mod 4)
#define NCHUNK ((MAX_LEN + CHUNK_ROWS - 1) / CHUNK_ROWS)  // 40
#define STAGE_WORDS (CHUNK_WORDS + 4)             // +shift padding (m <= 3)
#define NBUF 4
#define BOND_READY_CHUNK 23   // rows 0..12287 ⊇ sc[0..12287], sb[0..12284]
#define TOR1_READY_CHUNK 24   // first-half torsions: st rows <= 10244 ✓, coords ✓
#define ANG_READY_CHUNK  31   // rows 0..16383 ⊇ sa[0..16375]
#define TOR_SPLIT 2048        // torsion elements [0,2048) need st rows <= 10244

// Dynamic SMEM layout (bytes):
//   [0,      49152)  coords f32[12288]
//   [49152,  73728)  bond   u16[12288]  (12285 used)
//   [73728, 106496)  angle  u16[16384]  (16376 used)
//   [106496,147456)  tor    u16[20480]  (20465 used)
//   [147456,147840)  reduction f32[96]
//   [147840,221632)  staging: 4 x f32[4612] (16B-aligned bases)
#define SMEM_BYTES 221632

__device__ __forceinline__ void cp_async4(uint32_t saddr, const float* gaddr) {
    asm volatile("cp.async.ca.shared.global [%0], [%1], 4;\n"
                 :: "r"(saddr), "l"(gaddr));
}
__device__ __forceinline__ void cp_async16(uint32_t saddr, const float* gaddr) {
    asm volatile("cp.async.cg.shared.global [%0], [%1], 16;\n"
                 :: "r"(saddr), "l"(gaddr));
}
__device__ __forceinline__ void cp_commit() {
    asm volatile("cp.async.commit_group;\n" ::: "memory");
}
template <int N>
__device__ __forceinline__ void cp_wait() {
    asm volatile("cp.async.wait_group %0;\n" :: "n"(N) : "memory");
}

// Copy words [w0, w0+cnt) of fb into staging at word index (w - w0) + m,
// where m = sample word-offset mod 4. Head/tail scalar, body 16B vector:
//   global word w0+pre+4q is 16B-aligned (w0%4==0, (m+pre)%4==0),
//   smem word pre+m+4q is 16B-aligned ((pre+m)%4==0, base 16B-aligned).
__device__ __forceinline__ void copy_chunk(uint32_t sbase, const float* __restrict__ fb,
                                           int w0, int cnt, int m, int pre, int tid)
{
    if (tid < pre)
        cp_async4(sbase + 4u * (uint32_t)(tid + m), fb + w0 + tid);
    const int nv = (cnt - pre) >> 2;
    for (int q = tid; q < nv; q += NTHREADS)
        cp_async16(sbase + 4u * (uint32_t)(pre + m + 4 * q), fb + w0 + pre + 4 * q);
    const int done = pre + 4 * nv;
    const int rem  = cnt - done;   // 0..3
    if (tid >= 32 && tid < 32 + rem)
        cp_async4(sbase + 4u * (uint32_t)(done + m + (tid - 32)), fb + w0 + done + (tid - 32));
}

__global__ __launch_bounds__(NTHREADS, 1)
void local_energy_kernel(const float* __restrict__ feats,
                         const float* __restrict__ bond_type,   // [15,2]
                         const float* __restrict__ angle_type,  // [13,2]
                         const float* __restrict__ tor_type,    // [25,2]
                         const int*   __restrict__ multiplicity,// [25]
                         const float* __restrict__ opt_pars,    // [47]
                         float* __restrict__ out)               // [B,3]
{
    extern __shared__ unsigned char smem_raw[];
    float*          sc    = (float*)smem_raw;                     // coords
    unsigned short* sb    = (unsigned short*)(sc + COORD_ROWS);   // bond raw
    unsigned short* sa    = sb + 12288;                           // angle raw
    unsigned short* st    = sa + 16384;                           // tor raw
    float*          sred  = (float*)(st + 20480);                 // 96 floats
    float*          sstage = sred + 96;                           // 4 buffers

    __shared__ float s_bt[30];
    __shared__ float s_at[26];
    __shared__ float s_tt[50];
    __shared__ float s_mu[25];

    const int tid = threadIdx.x;
    const int b   = blockIdx.x;
    const float* fb = feats + (size_t)b * (size_t)TOTAL_WORDS;

    // fb word-offset mod 4 == b mod 4 (184185 == 1 mod 4; base 256B-aligned)
    const int m   = b & 3;            // staging shift (words)
    const int pre = (4 - m) & 3;      // scalar head words per chunk

    uint32_t stage_a[NBUF];
    float*   stage_p[NBUF];
    #pragma unroll
    for (int j = 0; j < NBUF; j++) {
        stage_p[j] = sstage + j * STAGE_WORDS;
        stage_a[j] = (uint32_t)__cvta_generic_to_shared(stage_p[j]);
    }

    if (tid < 30) s_bt[tid] = bond_type[tid];
    if (tid < 26) s_at[tid] = angle_type[tid];
    if (tid < 50) s_tt[tid] = tor_type[tid];
    if (tid < 25) s_mu[tid] = (float)multiplicity[tid];

    float e_bond = 0.0f, e_ang = 0.0f, e_tor = 0.0f;

    // ---- Phase 1: 4-deep pipelined cp.async stream + extract ----
    // prime: issue chunks 0,1,2 as separate groups
    #pragma unroll
    for (int c = 0; c < NBUF - 1; c++) {
        int w0 = c * CHUNK_WORDS;
        copy_chunk(stage_a[c], fb, w0, min(CHUNK_WORDS, TOTAL_WORDS - w0), m, pre, tid);
        cp_commit();
    }

    for (int k = 0; k < NCHUNK; k++) {
        // issue chunk k+3 into buffer (k+3)&3 (= (k-1)&3, extracted at iter
        // k-1; end-of-iter barrier separates); then wait until chunk k landed.
        if (k + 3 < NCHUNK) {
            int c  = k + 3;
            int w0 = c * CHUNK_WORDS;
            copy_chunk(stage_a[c & 3], fb, w0, min(CHUNK_WORDS, TOTAL_WORDS - w0), m, pre, tid);
            cp_commit();
            cp_wait<3>();
        } else if (k + 2 < NCHUNK) {
            cp_wait<2>();
        } else if (k + 1 < NCHUNK) {
            cp_wait<1>();
        } else {
            cp_wait<0>();
        }
        __syncthreads();    // chunk k visible to all threads

        // extract chunk k: threads [0,512) each handle one row; LDS lane
        // stride 9 words (9 coprime 32) -> conflict-free
        if (tid < CHUNK_ROWS) {
            int i = k * CHUNK_ROWS + tid;   // global row
            if (i < MAX_LEN) {
                const float* cur = stage_p[k & 3];
                int base = 9 * tid + m;
                float c5 = cur[base + 5];
                float c6 = cur[base + 6];
                float c7 = cur[base + 7];
                float c8 = cur[base + 8];
                if (i < COORD_ROWS) sc[i] = c5;
                if (i < BOND_ROWS)  sb[i] = (unsigned short)(int)c6;
                if (i < ANG_ROWS)   sa[i] = (unsigned short)(int)c7;
                st[i] = (unsigned short)(int)c8;
            }
        }
        __syncthreads();    // publishes tables; guards buffer reuse at iter k+1

        // ---- Bonds: sc, sb complete; hidden under in-flight copies ----
        if (k == BOND_READY_CHUNK) {
            for (int e = tid; e < NB; e += NTHREADS) {
                int i0 = sb[3 * e + 0];
                int i1 = sb[3 * e + 1];
                int t  = sb[3 * e + 2];
                float dx = sc[3 * i0 + 0] - sc[3 * i1 + 0];
                float dy = sc[3 * i0 + 1] - sc[3 * i1 + 1];
                float dz = sc[3 * i0 + 2] - sc[3 * i1 + 2];
                float r  = sqrtf(dx * dx + dy * dy + dz * dz + EPSF);
                float dr = r - s_bt[2 * t + 1];
                e_bond += s_bt[2 * t] * dr * dr;
            }
        }

        // ---- First-half torsions: st rows <= 10244 < 12800 extracted ----
        if (k == TOR1_READY_CHUNK) {
            for (int e = tid; e < TOR_SPLIT; e += NTHREADS) {
                int ii = st[5 * e + 0];
                int jj = st[5 * e + 1];
                int kk = st[5 * e + 2];
                int ll = st[5 * e + 3];
                int t  = st[5 * e + 4];
                float cix = sc[3 * ii + 0], ciy = sc[3 * ii + 1], ciz = sc[3 * ii + 2];
                float cjx = sc[3 * jj + 0], cjy = sc[3 * jj + 1], cjz = sc[3 * jj + 2];
                float ckx = sc[3 * kk + 0], cky = sc[3 * kk + 1], ckz = sc[3 * kk + 2];
                float clx = sc[3 * ll + 0], cly = sc[3 * ll + 1], clz = sc[3 * ll + 2];
                float b1x = cjx - cix, b1y = cjy - ciy, b1z = cjz - ciz;
                float b2x = ckx - cjx, b2y = cky - cjy, b2z = ckz - cjz;
                float b3x = clx - ckx, b3y = cly - cky, b3z = clz - ckz;
                float n1x = b1y * b2z - b1z * b2y;
                float n1y = b1z * b2x - b1x * b2z;
                float n1z = b1x * b2y - b1y * b2x;
                float n2x = b2y * b3z - b2z * b3y;
                float n2y = b2z * b3x - b2x * b3z;
                float n2z = b2x * b3y - b2y * b3x;
                float inv = 1.0f / sqrtf(b2x * b2x + b2y * b2y + b2z * b2z + EPSF);
                float bnx = b2x * inv, bny = b2y * inv, bnz = b2z * inv;
                float m1x = n1y * bnz - n1z * bny;
                float m1y = n1z * bnx - n1x * bnz;
                float m1z = n1x * bny - n1y * bnx;
                float yv = m1x * n2x + m1y * n2y + m1z * n2z;
                float xv = n1x * n2x + n1y * n2y + n1z * n2z;
                float phi = atan2f(yv, xv);
                float arg = s_mu[t] * phi - s_tt[2 * t + 1];
                e_tor += s_tt[2 * t] * (1.0f + cosf(arg));
            }
        }

        // ---- Angles: sa complete; hidden under in-flight copies ----
        if (k == ANG_READY_CHUNK) {
            for (int e = tid; e < NA; e += NTHREADS) {
                int a0 = sa[4 * e + 0];
                int a1 = sa[4 * e + 1];
                int a2 = sa[4 * e + 2];
                int t  = sa[4 * e + 3];
                float cx = sc[3 * a1 + 0], cy = sc[3 * a1 + 1], cz = sc[3 * a1 + 2];
                float x1 = sc[3 * a0 + 0] - cx;
                float y1 = sc[3 * a0 + 1] - cy;
                float z1 = sc[3 * a0 + 2] - cz;
                float x2 = sc[3 * a2 + 0] - cx;
                float y2 = sc[3 * a2 + 1] - cy;
                float z2 = sc[3 * a2 + 2] - cz;
                float d11 = x1 * x1 + y1 * y1 + z1 * z1 + EPSF;
                float d22 = x2 * x2 + y2 * y2 + z2 * z2 + EPSF;
                float dt  = x1 * x2 + y1 * y2 + z1 * z2;
                float cosang = dt / (sqrtf(d11) * sqrtf(d22));
                cosang = fminf(fmaxf(cosang, -0.999999f), 0.999999f);
                float theta = acosf(cosang);
                float dth = theta - s_at[2 * t + 1];
                e_ang += s_at[2 * t] * dth * dth;
            }
        }
    }

    // ---- Second-half torsions (need the last chunk; inherent tail) ----
    for (int e = TOR_SPLIT + tid; e < NT; e += NTHREADS) {
        int ii = st[5 * e + 0];
        int jj = st[5 * e + 1];
        int kk = st[5 * e + 2];
        int ll = st[5 * e + 3];
        int t  = st[5 * e + 4];
        float cix = sc[3 * ii + 0], ciy = sc[3 * ii + 1], ciz = sc[3 * ii + 2];
        float cjx = sc[3 * jj + 0], cjy = sc[3 * jj + 1], cjz = sc[3 * jj + 2];
        float ckx = sc[3 * kk + 0], cky = sc[3 * kk + 1], ckz = sc[3 * kk + 2];
        float clx = sc[3 * ll + 0], cly = sc[3 * ll + 1], clz = sc[3 * ll + 2];
        float b1x = cjx - cix, b1y = cjy - ciy, b1z = cjz - ciz;
        float b2x = ckx - cjx, b2y = cky - cjy, b2z = ckz - cjz;
        float b3x = clx - ckx, b3y = cly - cky, b3z = clz - ckz;
        float n1x = b1y * b2z - b1z * b2y;
        float n1y = b1z * b2x - b1x * b2z;
        float n1z = b1x * b2y - b1y * b2x;
        float n2x = b2y * b3z - b2z * b3y;
        float n2y = b2z * b3x - b2x * b3z;
        float n2z = b2x * b3y - b2y * b3x;
        float inv = 1.0f / sqrtf(b2x * b2x + b2y * b2y + b2z * b2z + EPSF);
        float bnx = b2x * inv, bny = b2y * inv, bnz = b2z * inv;
        float m1x = n1y * bnz - n1z * bny;
        float m1y = n1z * bnx - n1x * bnz;
        float m1z = n1x * bny - n1y * bnx;
        float yv = m1x * n2x + m1y * n2y + m1z * n2z;
        float xv = n1x * n2x + n1y * n2y + n1z * n2z;
        float phi = atan2f(yv, xv);
        float arg = s_mu[t] * phi - s_tt[2 * t + 1];
        e_tor += s_tt[2 * t] * (1.0f + cosf(arg));
    }

    // ---- Deterministic block reduction ----
    #pragma unroll
    for (int off = 16; off > 0; off >>= 1) {
        e_bond += __shfl_down_sync(0xffffffffu, e_bond, off);
        e_ang  += __shfl_down_sync(0xffffffffu, e_ang,  off);
        e_tor  += __shfl_down_sync(0xffffffffu, e_tor,  off);
    }
    const int warp = tid >> 5;
    const int lane = tid & 31;
    if (lane == 0) {
        sred[warp]      = e_bond;
        sred[32 + warp] = e_ang;
        sred[64 + warp] = e_tor;
    }
    __syncthreads();
    if (warp == 0) {
        float eb = sred[lane];
        float ea = sred[32 + lane];
        float et = sred[64 + lane];
        #pragma unroll
        for (int off = 16; off > 0; off >>= 1) {
            eb += __shfl_down_sync(0xffffffffu, eb, off);
            ea += __shfl_down_sync(0xffffffffu, ea, off);
            et += __shfl_down_sync(0xffffffffu, et, off);
        }
        if (lane == 0) {
            out[b * 3 + 0] = opt_pars[0] * eb;
            out[b * 3 + 1] = opt_pars[1] * ea;
            out[b * 3 + 2] = opt_pars[2] * et;
        }
    }
}

extern "C" void kernel_launch(void* const* d_in, const int* in_sizes, int n_in,
                              void* d_out, int out_size)
{
    (void)in_sizes; (void)n_in; (void)out_size;
    const float* feats        = (const float*)d_in[0];
    // d_in[1] = lengths (unused: reference uses fixed compile-time slices)
    const float* bond_type    = (const float*)d_in[2];
    const float* angle_type   = (const float*)d_in[3];
    const float* tor_type     = (const float*)d_in[4];
    const int*   multiplicity = (const int*)d_in[5];
    const float* opt_pars     = (const float*)d_in[6];
    float* out = (float*)d_out;

    cudaFuncSetAttribute(local_energy_kernel,
                         cudaFuncAttributeMaxDynamicSharedMemorySize, SMEM_BYTES);

    local_energy_kernel<<<128, NTHREADS, SMEM_BYTES>>>(
        feats, bond_type, angle_type, tor_type, multiplicity, opt_pars, out);
}

// round 14
// speedup vs baseline: 2.4298x; 2.4298x over previous
#include <cuda_runtime.h>
#include <cstdint>

// Problem constants (match reference)
#define N_ATOMS 4096
#define NB 4095
#define NA 4094
#define NT 4093
#define MAX_LEN (5 * NT)          // 20465 rows
#define TOTAL_WORDS (MAX_LEN * 9) // 184185 words per sample
#define COORD_ROWS (3 * N_ATOMS)  // 12288
#define BOND_ROWS  (3 * NB)       // 12285
#define ANG_ROWS   (4 * NA)       // 16376
#define EPSF 1e-8f

#define NTHREADS 1024
#define NWARPS 32
#define ROWS_PER_BLK 32
#define WORDS_PER_BLK (ROWS_PER_BLK * 9)     // 288
#define NBLK ((MAX_LEN + ROWS_PER_BLK - 1) / ROWS_PER_BLK)  // 640
#define BLKS_PER_WARP (NBLK / NWARPS)        // 20 exactly

// Warp-specialized compute split
#define BOND_W0 0
#define BOND_NW 6
#define ANG_W0  6
#define ANG_NW  10
#define TOR_W0  16
#define TOR_NW  16

// Dynamic SMEM layout (bytes):
//   [0,      49152)  coords f32[12288]
//   [49152,  73728)  bond   u16[12288]  (12285 used)
//   [73728, 106496)  angle  u16[16384]  (16376 used)
//   [106496,147456)  tor    u16[20480]  (20465 used)
//   [147456,147840)  reduction f32[96]
//   [147840,184704)  per-warp staging: 32 x f32[288]
#define SMEM_BYTES 184704

__global__ __launch_bounds__(NTHREADS, 1)
void local_energy_kernel(const float* __restrict__ feats,
                         const float* __restrict__ bond_type,   // [15,2]
                         const float* __restrict__ angle_type,  // [13,2]
                         const float* __restrict__ tor_type,    // [25,2]
                         const int*   __restrict__ multiplicity,// [25]
                         const float* __restrict__ opt_pars,    // [47]
                         float* __restrict__ out)               // [B,3]
{
    extern __shared__ unsigned char smem_raw[];
    float*          sc    = (float*)smem_raw;                     // coords
    unsigned short* sb    = (unsigned short*)(sc + COORD_ROWS);   // bond raw
    unsigned short* sa    = sb + 12288;                           // angle raw
    unsigned short* st    = sa + 16384;                           // tor raw
    float*          sred  = (float*)(st + 20480);                 // 96 floats
    float*          sstage = sred + 96;                           // 32 x 288

    __shared__ float s_bt[30];
    __shared__ float s_at[26];
    __shared__ float s_tt[50];
    __shared__ float s_mu[25];

    const int tid  = threadIdx.x;
    const int w    = tid >> 5;
    const int lane = tid & 31;
    const int b    = blockIdx.x;
    const float* fb = feats + (size_t)b * (size_t)TOTAL_WORDS;

    float* stg = sstage + w * WORDS_PER_BLK;   // warp-private staging

    if (tid < 30) s_bt[tid] = bond_type[tid];
    if (tid < 26) s_at[tid] = angle_type[tid];
    if (tid < 50) s_tt[tid] = tor_type[tid];
    if (tid < 25) s_mu[tid] = (float)multiplicity[tid];

    // ---- Phase 1: per-warp autonomous stream (no block barriers) ----
    // Warp w handles blocks w, w+32, ..., w+608 (20 blocks of 32 rows).
    // Depth-3 register prefetch: block j is consumed two warp-iterations
    // after its 9 LDGs were issued (~800 cyc cover > DRAM latency).
    // Per block: 9 STS to private staging, syncwarp, 4 LDS per row
    // (stride 9 coprime 32 -> conflict-free), guarded table stores, syncwarp.
    {
        float buf[3][9];   // fully-unrolled loop => static indices => registers

        // prologue: load blocks j=0,1 for this warp
        #pragma unroll
        for (int jj = 0; jj < 2; jj++) {
            int w0 = WORDS_PER_BLK * (w + 32 * jj);
            #pragma unroll
            for (int q = 0; q < 9; q++) {
                int word = w0 + q * 32 + lane;
                buf[jj][q] = (word < TOTAL_WORDS) ? __ldg(fb + word) : 0.0f;
            }
        }

        #pragma unroll
        for (int j = 0; j < BLKS_PER_WARP; j++) {
            // prefetch block j+2 into buf[(j+2)%3] (consumed 2 iters later)
            if (j + 2 < BLKS_PER_WARP) {
                int w0 = WORDS_PER_BLK * (w + 32 * (j + 2));
                #pragma unroll
                for (int q = 0; q < 9; q++) {
                    int word = w0 + q * 32 + lane;
                    buf[(j + 2) % 3][q] = (word < TOTAL_WORDS) ? __ldg(fb + word) : 0.0f;
                }
            }

            // stage block j (its LDGs issued 2 iterations ago)
            #pragma unroll
            for (int q = 0; q < 9; q++)
                stg[q * 32 + lane] = buf[j % 3][q];
            __syncwarp();

            // extract: lane handles row 32*blk + lane
            {
                int i = 32 * (w + 32 * j) + lane;
                if (i < MAX_LEN) {
                    int base = 9 * lane;
                    float c5 = stg[base + 5];
                    float c6 = stg[base + 6];
                    float c7 = stg[base + 7];
                    float c8 = stg[base + 8];
                    if (i < COORD_ROWS) sc[i] = c5;
                    if (i < BOND_ROWS)  sb[i] = (unsigned short)(int)c6;
                    if (i < ANG_ROWS)   sa[i] = (unsigned short)(int)c7;
                    st[i] = (unsigned short)(int)c8;
                }
            }
            __syncwarp();   // staging reuse guard
        }
    }

    __syncthreads();   // all tables complete & visible

    float e_bond = 0.0f, e_ang = 0.0f, e_tor = 0.0f;

    // ---- Phase 2: warp-specialized compute (phases run concurrently) ----
    if (w < ANG_W0) {
        // Bonds: warps [0,6), 192 lanes
        const int g = w * 32 + lane;
        for (int e = g; e < NB; e += BOND_NW * 32) {
            int i0 = sb[3 * e + 0];
            int i1 = sb[3 * e + 1];
            int t  = sb[3 * e + 2];
            float dx = sc[3 * i0 + 0] - sc[3 * i1 + 0];
            float dy = sc[3 * i0 + 1] - sc[3 * i1 + 1];
            float dz = sc[3 * i0 + 2] - sc[3 * i1 + 2];
            float r  = sqrtf(dx * dx + dy * dy + dz * dz + EPSF);
            float dr = r - s_bt[2 * t + 1];
            e_bond += s_bt[2 * t] * dr * dr;
        }
    } else if (w < TOR_W0) {
        // Angles: warps [6,16), 320 lanes
        const int g = (w - ANG_W0) * 32 + lane;
        for (int e = g; e < NA; e += ANG_NW * 32) {
            int a0 = sa[4 * e + 0];
            int a1 = sa[4 * e + 1];
            int a2 = sa[4 * e + 2];
            int t  = sa[4 * e + 3];
            float cx = sc[3 * a1 + 0], cy = sc[3 * a1 + 1], cz = sc[3 * a1 + 2];
            float x1 = sc[3 * a0 + 0] - cx;
            float y1 = sc[3 * a0 + 1] - cy;
            float z1 = sc[3 * a0 + 2] - cz;
            float x2 = sc[3 * a2 + 0] - cx;
            float y2 = sc[3 * a2 + 1] - cy;
            float z2 = sc[3 * a2 + 2] - cz;
            float d11 = x1 * x1 + y1 * y1 + z1 * z1 + EPSF;
            float d22 = x2 * x2 + y2 * y2 + z2 * z2 + EPSF;
            float dt  = x1 * x2 + y1 * y2 + z1 * z2;
            float cosang = dt / (sqrtf(d11) * sqrtf(d22));
            cosang = fminf(fmaxf(cosang, -0.999999f), 0.999999f);
            float theta = acosf(cosang);
            float dth = theta - s_at[2 * t + 1];
            e_ang += s_at[2 * t] * dth * dth;
        }
    } else {
        // Torsions: warps [16,32), 512 lanes
        const int g = (w - TOR_W0) * 32 + lane;
        for (int e = g; e < NT; e += TOR_NW * 32) {
            int ii = st[5 * e + 0];
            int jj = st[5 * e + 1];
            int kk = st[5 * e + 2];
            int ll = st[5 * e + 3];
            int t  = st[5 * e + 4];
            float cix = sc[3 * ii + 0], ciy = sc[3 * ii + 1], ciz = sc[3 * ii + 2];
            float cjx = sc[3 * jj + 0], cjy = sc[3 * jj + 1], cjz = sc[3 * jj + 2];
            float ckx = sc[3 * kk + 0], cky = sc[3 * kk + 1], ckz = sc[3 * kk + 2];
            float clx = sc[3 * ll + 0], cly = sc[3 * ll + 1], clz = sc[3 * ll + 2];
            float b1x = cjx - cix, b1y = cjy - ciy, b1z = cjz - ciz;
            float b2x = ckx - cjx, b2y = cky - cjy, b2z = ckz - cjz;
            float b3x = clx - ckx, b3y = cly - cky, b3z = clz - ckz;
            float n1x = b1y * b2z - b1z * b2y;
            float n1y = b1z * b2x - b1x * b2z;
            float n1z = b1x * b2y - b1y * b2x;
            float n2x = b2y * b3z - b2z * b3y;
            float n2y = b2z * b3x - b2x * b3z;
            float n2z = b2x * b3y - b2y * b3x;
            float inv = 1.0f / sqrtf(b2x * b2x + b2y * b2y + b2z * b2z + EPSF);
            float bnx = b2x * inv, bny = b2y * inv, bnz = b2z * inv;
            float m1x = n1y * bnz - n1z * bny;
            float m1y = n1z * bnx - n1x * bnz;
            float m1z = n1x * bny - n1y * bnx;
            float yv = m1x * n2x + m1y * n2y + m1z * n2z;
            float xv = n1x * n2x + n1y * n2y + n1z * n2z;
            float phi = atan2f(yv, xv);
            float arg = s_mu[t] * phi - s_tt[2 * t + 1];
            e_tor += s_tt[2 * t] * (1.0f + cosf(arg));
        }
    }

    // ---- Deterministic block reduction ----
    #pragma unroll
    for (int off = 16; off > 0; off >>= 1) {
        e_bond += __shfl_down_sync(0xffffffffu, e_bond, off);
        e_ang  += __shfl_down_sync(0xffffffffu, e_ang,  off);
        e_tor  += __shfl_down_sync(0xffffffffu, e_tor,  off);
    }
    if (lane == 0) {
        sred[w]      = e_bond;
        sred[32 + w] = e_ang;
        sred[64 + w] = e_tor;
    }
    __syncthreads();
    if (w == 0) {
        float eb = sred[lane];
        float ea = sred[32 + lane];
        float et = sred[64 + lane];
        #pragma unroll
        for (int off = 16; off > 0; off >>= 1) {
            eb += __shfl_down_sync(0xffffffffu, eb, off);
            ea += __shfl_down_sync(0xffffffffu, ea, off);
            et += __shfl_down_sync(0xffffffffu, et, off);
        }
        if (lane == 0) {
            out[b * 3 + 0] = opt_pars[0] * eb;
            out[b * 3 + 1] = opt_pars[1] * ea;
            out[b * 3 + 2] = opt_pars[2] * et;
        }
    }
}

extern "C" void kernel_launch(void* const* d_in, const int* in_sizes, int n_in,
                              void* d_out, int out_size)
{
    (void)in_sizes; (void)n_in; (void)out_size;
    const float* feats        = (const float*)d_in[0];
    // d_in[1] = lengths (unused: reference uses fixed compile-time slices)
    const float* bond_type    = (const float*)d_in[2];
    const float* angle_type   = (const float*)d_in[3];
    const float* tor_type     = (const float*)d_in[4];
    const int*   multiplicity = (const int*)d_in[5];
    const float* opt_pars     = (const float*)d_in[6];
    float* out = (float*)d_out;

    cudaFuncSetAttribute(local_energy_kernel,
                         cudaFuncAttributeMaxDynamicSharedMemorySize, SMEM_BYTES);

    local_energy_kernel<<<128, NTHREADS, SMEM_BYTES>>>(
        feats, bond_type, angle_type, tor_type, multiplicity, opt_pars, out);
}